// round 1
// baseline (speedup 1.0000x reference)
#include <cuda_runtime.h>
#include <math.h>

// ---------------- problem constants ----------------
#define D_MODEL 2048
#define D_STATE 16
#define D_CONV 4
#define D_INNER 4096
#define DT_RANK 128
#define BATCH 2
#define SEQLEN 1024
#define M_ROWS (BATCH * SEQLEN)              // 2048 tokens
#define XDBL_COLS (DT_RANK + 2 * D_STATE)    // 160

// ---------------- scratch (static device globals; no allocation) ----------------
__device__ float g_xz[(size_t)M_ROWS * 2 * D_INNER];   // 2048 x 8192
__device__ float g_xc[(size_t)M_ROWS * D_INNER];       // conv+silu output
__device__ float g_xdbl[(size_t)M_ROWS * XDBL_COLS];   // dt | B | C
__device__ float g_delta[(size_t)M_ROWS * D_INNER];    // softplus(dt @ W + b)
__device__ float g_y[(size_t)M_ROWS * D_INNER];        // scan output -> gated

// ---------------------------------------------------------------------------
// SGEMM: C[m,n] = sum_k A[m*lda+k] * W[n*ldw+k]   (C = A @ W^T)
// 128x128 tile, BK=8, 256 threads, 8x8 per-thread microtile.
// M assumed multiple of 128 (always 2048 here). N guarded (x_proj has N=160).
// K assumed multiple of 8 and lda/ldw multiples of 4 (true for all calls).
// ---------------------------------------------------------------------------
__global__ __launch_bounds__(256) void sgemm_nt(
    const float* __restrict__ A, int lda,
    const float* __restrict__ W, int ldw,
    float* __restrict__ C, int ldc,
    int N, int K)
{
    const int BM = 128, BN = 128, BK = 8;
    __shared__ float As[BK][BM];
    __shared__ float Bs[BK][BN];

    const int tid = threadIdx.x;
    const int m0 = blockIdx.y * BM;
    const int n0 = blockIdx.x * BN;
    const int tx = tid & 15;        // 0..15 -> n
    const int ty = tid >> 4;        // 0..15 -> m

    const int loadRow = tid >> 1;          // 0..127
    const int loadK   = (tid & 1) * 4;     // 0 or 4

    float acc[8][8];
#pragma unroll
    for (int i = 0; i < 8; i++)
#pragma unroll
        for (int j = 0; j < 8; j++) acc[i][j] = 0.f;

    const int nrow = n0 + loadRow;
    const float* aBase = A + (size_t)(m0 + loadRow) * lda + loadK;
    const float* wBase = W + (size_t)nrow * ldw + loadK;

    for (int k0 = 0; k0 < K; k0 += BK) {
        float4 av = *(const float4*)(aBase + k0);
        float4 wv = make_float4(0.f, 0.f, 0.f, 0.f);
        if (nrow < N) wv = *(const float4*)(wBase + k0);

        As[loadK + 0][loadRow] = av.x;
        As[loadK + 1][loadRow] = av.y;
        As[loadK + 2][loadRow] = av.z;
        As[loadK + 3][loadRow] = av.w;
        Bs[loadK + 0][loadRow] = wv.x;
        Bs[loadK + 1][loadRow] = wv.y;
        Bs[loadK + 2][loadRow] = wv.z;
        Bs[loadK + 3][loadRow] = wv.w;
        __syncthreads();

#pragma unroll
        for (int k = 0; k < BK; k++) {
            float a[8], b[8];
            *(float4*)&a[0] = *(const float4*)&As[k][ty * 8];
            *(float4*)&a[4] = *(const float4*)&As[k][ty * 8 + 4];
            *(float4*)&b[0] = *(const float4*)&Bs[k][tx * 8];
            *(float4*)&b[4] = *(const float4*)&Bs[k][tx * 8 + 4];
#pragma unroll
            for (int i = 0; i < 8; i++)
#pragma unroll
                for (int j = 0; j < 8; j++)
                    acc[i][j] = fmaf(a[i], b[j], acc[i][j]);
        }
        __syncthreads();
    }

#pragma unroll
    for (int i = 0; i < 8; i++) {
        const int row = m0 + ty * 8 + i;
#pragma unroll
        for (int j = 0; j < 8; j++) {
            const int col = n0 + tx * 8 + j;
            if (col < N) C[(size_t)row * ldc + col] = acc[i][j];
        }
    }
}

// ---------------------------------------------------------------------------
// Causal depthwise conv (K=4) + SiLU.  x = g_xz[:, 0:D_INNER] -> g_xc
// ---------------------------------------------------------------------------
__global__ void conv_silu_kernel(const float* __restrict__ conv_w,
                                 const float* __restrict__ conv_b)
{
    int idx = blockIdx.x * blockDim.x + threadIdx.x;
    if (idx >= M_ROWS * D_INNER) return;
    int d = idx & (D_INNER - 1);
    int row = idx >> 12;                 // token index b*L + l
    int l = row & (SEQLEN - 1);

    float acc = conv_b[d];
#pragma unroll
    for (int k = 0; k < D_CONV; k++) {
        int ll = l + k - (D_CONV - 1);
        if (ll >= 0)
            acc = fmaf(g_xz[(size_t)(row + k - (D_CONV - 1)) * (2 * D_INNER) + d],
                       conv_w[d * D_CONV + k], acc);
    }
    float s = acc / (1.f + expf(-acc));  // SiLU
    g_xc[idx] = s;
}

// ---------------------------------------------------------------------------
// delta = softplus(delta_raw + dt_proj_b[d])
// ---------------------------------------------------------------------------
__global__ void dt_softplus_kernel(const float* __restrict__ dt_b)
{
    int idx = blockIdx.x * blockDim.x + threadIdx.x;
    if (idx >= M_ROWS * D_INNER) return;
    int d = idx & (D_INNER - 1);
    float v = g_delta[idx] + dt_b[d];
    g_delta[idx] = (v > 20.f) ? v : log1pf(expf(v));
}

// ---------------------------------------------------------------------------
// Selective scan: one 16-lane group per (b, d) channel, one lane per state n.
// ---------------------------------------------------------------------------
__global__ __launch_bounds__(256) void scan_kernel(const float* __restrict__ A)
{
    int t = blockIdx.x * blockDim.x + threadIdx.x;
    int lane = t & (D_STATE - 1);
    int grp = t >> 4;
    if (grp >= BATCH * D_INNER) return;
    int d = grp & (D_INNER - 1);
    int b = grp >> 12;

    const float a_l2e = A[d * D_STATE + lane] * 1.44269504088896341f;
    const float* dptr = g_delta + (size_t)b * SEQLEN * D_INNER + d;
    const float* xptr = g_xc + (size_t)b * SEQLEN * D_INNER + d;
    const float* bc = g_xdbl + (size_t)b * SEQLEN * XDBL_COLS;
    float* yp = g_y + (size_t)b * SEQLEN * D_INNER + d;

    float state = 0.f;
    for (int l = 0; l < SEQLEN; l++) {
        float dt = dptr[(size_t)l * D_INNER];               // uniform across lanes
        float xv = xptr[(size_t)l * D_INNER];               // uniform across lanes
        float Bn = bc[l * XDBL_COLS + DT_RANK + lane];
        float Cn = bc[l * XDBL_COLS + DT_RANK + D_STATE + lane];

        float dA = exp2f(dt * a_l2e);                        // exp(dt * A[n])
        state = fmaf(dA, state, dt * Bn * xv);
        float yv = state * Cn;
        yv += __shfl_xor_sync(0xffffffffu, yv, 8);
        yv += __shfl_xor_sync(0xffffffffu, yv, 4);
        yv += __shfl_xor_sync(0xffffffffu, yv, 2);
        yv += __shfl_xor_sync(0xffffffffu, yv, 1);
        if (lane == 0) yp[(size_t)l * D_INNER] = yv;
    }
}

// ---------------------------------------------------------------------------
// y = (y + xc * D[d]) * silu(z)
// ---------------------------------------------------------------------------
__global__ void gate_kernel(const float* __restrict__ Dp)
{
    int idx = blockIdx.x * blockDim.x + threadIdx.x;
    if (idx >= M_ROWS * D_INNER) return;
    int d = idx & (D_INNER - 1);
    int row = idx >> 12;
    float z = g_xz[(size_t)row * (2 * D_INNER) + D_INNER + d];
    float sz = z / (1.f + expf(-z));
    g_y[idx] = fmaf(g_xc[idx], Dp[d], g_y[idx]) * sz;
}

// ---------------------------------------------------------------------------
// launch
// ---------------------------------------------------------------------------
extern "C" void kernel_launch(void* const* d_in, const int* in_sizes, int n_in,
                              void* d_out, int out_size)
{
    const float* hidden    = (const float*)d_in[0];  // (B, L, D_MODEL)
    const float* in_proj_w = (const float*)d_in[1];  // (2*D_INNER, D_MODEL)
    const float* conv_w    = (const float*)d_in[2];  // (D_INNER, D_CONV)
    const float* conv_b    = (const float*)d_in[3];  // (D_INNER,)
    const float* x_proj_w  = (const float*)d_in[4];  // (XDBL_COLS, D_INNER)
    const float* dt_proj_w = (const float*)d_in[5];  // (D_INNER, DT_RANK)
    const float* dt_proj_b = (const float*)d_in[6];  // (D_INNER,)
    const float* out_proj_w= (const float*)d_in[7];  // (D_MODEL, D_INNER)
    const float* A_mat     = (const float*)d_in[8];  // (D_INNER, D_STATE)
    const float* D_param   = (const float*)d_in[9];  // (D_INNER,)
    float* out = (float*)d_out;

    float *p_xz, *p_xc, *p_xdbl, *p_delta, *p_y;
    cudaGetSymbolAddress((void**)&p_xz, g_xz);
    cudaGetSymbolAddress((void**)&p_xc, g_xc);
    cudaGetSymbolAddress((void**)&p_xdbl, g_xdbl);
    cudaGetSymbolAddress((void**)&p_delta, g_delta);
    cudaGetSymbolAddress((void**)&p_y, g_y);

    const int elemThreads = 256;
    const int elemBlocks = (M_ROWS * D_INNER + elemThreads - 1) / elemThreads;

    // 1) xz = hidden @ in_proj_w^T : (2048, 8192), K=2048
    {
        dim3 grid((2 * D_INNER) / 128, M_ROWS / 128);
        sgemm_nt<<<grid, 256>>>(hidden, D_MODEL, in_proj_w, D_MODEL,
                                p_xz, 2 * D_INNER, 2 * D_INNER, D_MODEL);
    }
    // 2) causal depthwise conv + SiLU
    conv_silu_kernel<<<elemBlocks, elemThreads>>>(conv_w, conv_b);

    // 3) x_dbl = xc @ x_proj_w^T : (2048, 160), K=4096
    {
        dim3 grid((XDBL_COLS + 127) / 128, M_ROWS / 128);
        sgemm_nt<<<grid, 256>>>(p_xc, D_INNER, x_proj_w, D_INNER,
                                p_xdbl, XDBL_COLS, XDBL_COLS, D_INNER);
    }
    // 4) delta_raw = dt @ dt_proj_w^T : (2048, 4096), K=128 (dt = x_dbl[:, :128])
    {
        dim3 grid(D_INNER / 128, M_ROWS / 128);
        sgemm_nt<<<grid, 256>>>(p_xdbl, XDBL_COLS, dt_proj_w, DT_RANK,
                                p_delta, D_INNER, D_INNER, DT_RANK);
    }
    // 5) softplus(delta + b)
    dt_softplus_kernel<<<elemBlocks, elemThreads>>>(dt_proj_b);

    // 6) selective scan
    {
        int threads = BATCH * D_INNER * D_STATE;   // 131072
        scan_kernel<<<threads / 256, 256>>>(A_mat);
    }
    // 7) gate
    gate_kernel<<<elemBlocks, elemThreads>>>(D_param);

    // 8) out = y @ out_proj_w^T : (2048, 2048), K=4096
    {
        dim3 grid(D_MODEL / 128, M_ROWS / 128);
        sgemm_nt<<<grid, 256>>>(p_y, D_INNER, out_proj_w, D_INNER,
                                out, D_MODEL, D_MODEL, D_INNER);
    }
}

// round 3
// speedup vs baseline: 2.2131x; 2.2131x over previous
#include <cuda_runtime.h>
#include <cuda_bf16.h>
#include <math.h>
#include <stdint.h>

// ---------------- problem constants ----------------
#define D_MODEL 2048
#define D_STATE 16
#define D_CONV 4
#define D_INNER 4096
#define DT_RANK 128
#define BATCH 2
#define SEQLEN 1024
#define M_ROWS (BATCH * SEQLEN)              // 2048 tokens
#define XDBL_COLS (DT_RANK + 2 * D_STATE)    // 160

// ---------------- scratch (static device globals; no allocation) ----------------
__device__ float g_xz[(size_t)M_ROWS * 2 * D_INNER];
__device__ float g_xc[(size_t)M_ROWS * D_INNER];
__device__ float g_xdbl[(size_t)M_ROWS * XDBL_COLS];
__device__ float g_delta[(size_t)M_ROWS * D_INNER];
__device__ float g_y[(size_t)M_ROWS * D_INNER];

// split-bf16 triple buffers: [R][3K].  A-mode: [hi|lo|hi].  B-mode: [hi|hi|lo].
__device__ __nv_bfloat16 s_a_in [(size_t)M_ROWS * 3 * D_MODEL];
__device__ __nv_bfloat16 s_w_in [(size_t)(2 * D_INNER) * 3 * D_MODEL];
__device__ __nv_bfloat16 s_a_x  [(size_t)M_ROWS * 3 * D_INNER];
__device__ __nv_bfloat16 s_w_x  [(size_t)XDBL_COLS * 3 * D_INNER];
__device__ __nv_bfloat16 s_a_dt [(size_t)M_ROWS * 3 * DT_RANK];
__device__ __nv_bfloat16 s_w_dt [(size_t)D_INNER * 3 * DT_RANK];
__device__ __nv_bfloat16 s_a_out[(size_t)M_ROWS * 3 * D_INNER];
__device__ __nv_bfloat16 s_w_out[(size_t)D_MODEL * 3 * D_INNER];

// =====================================================================
// helpers
// =====================================================================
__device__ __forceinline__ uint32_t smem_u32(const void* p) {
    uint32_t a;
    asm("{ .reg .u64 t; cvta.to.shared.u64 t, %1; cvt.u32.u64 %0, t; }" : "=r"(a) : "l"(p));
    return a;
}
__device__ __forceinline__ void cp_async16(uint32_t dst, const void* src) {
    asm volatile("cp.async.cg.shared.global [%0], [%1], 16;" :: "r"(dst), "l"(src));
}
__device__ __forceinline__ void cp_commit() { asm volatile("cp.async.commit_group;" ::: "memory"); }
template <int N> __device__ __forceinline__ void cp_wait() {
    asm volatile("cp.async.wait_group %0;" :: "n"(N) : "memory");
}
__device__ __forceinline__ void ldsm4(uint32_t* r, uint32_t addr) {
    asm volatile("ldmatrix.sync.aligned.m8n8.x4.shared.b16 {%0,%1,%2,%3}, [%4];"
                 : "=r"(r[0]), "=r"(r[1]), "=r"(r[2]), "=r"(r[3]) : "r"(addr));
}
__device__ __forceinline__ void mma_bf16(float* d, const uint32_t* a, const uint32_t* b) {
    asm volatile(
        "mma.sync.aligned.m16n8k16.row.col.f32.bf16.bf16.f32 "
        "{%0,%1,%2,%3}, {%4,%5,%6,%7}, {%8,%9}, {%0,%1,%2,%3};"
        : "+f"(d[0]), "+f"(d[1]), "+f"(d[2]), "+f"(d[3])
        : "r"(a[0]), "r"(a[1]), "r"(a[2]), "r"(a[3]), "r"(b[0]), "r"(b[1]));
}

// =====================================================================
// bf16 split GEMM:  C[M,N] fp32 = A3[M,K3] @ B3[N,K3]^T
// BM=128 BN=128 BK=32, 4-stage cp.async, 8 warps (4m x 2n), warp tile 32x64.
// SMEM per stage: A 128x32 bf16 (8KB) + B 128x32 bf16 (8KB).
// 16B-chunk swizzle: chunk' = chunk ^ ((row>>1)&3); conflict-free for
// cp.async stores and ldmatrix reads.
// =====================================================================
#define BM 128
#define BN 128
#define BK 32
#define STAGES 4
#define STAGE_BYTES (16384)
#define A_OFF 0
#define B_OFF 8192
#define MM_SMEM (STAGES * STAGE_BYTES)

__device__ __forceinline__ uint32_t sw_addr(uint32_t base, int row, int kcol) {
    // kcol in bf16 elements (multiple of 8); 16B chunk = kcol>>3
    int ch = (kcol >> 3) ^ ((row >> 1) & 3);
    return base + row * 64 + (ch << 4);
}

__device__ __forceinline__ void mm_load_stage(
    uint32_t sb, const __nv_bfloat16* __restrict__ A3, const __nv_bfloat16* __restrict__ B3,
    int K3, int m0, int n0, int N, int kk, int tid)
{
#pragma unroll
    for (int i = 0; i < 2; i++) {
        int q = tid + i * 256;                 // 0..511
        int r = q >> 2, c = q & 3;
        const __nv_bfloat16* g = A3 + (size_t)(m0 + r) * K3 + kk + c * 8;
        cp_async16(sw_addr(sb + A_OFF, r, c * 8), g);
    }
#pragma unroll
    for (int i = 0; i < 2; i++) {
        int q = tid + i * 256;
        int r = q >> 2, c = q & 3;
        int row = n0 + r; if (row >= N) row = N - 1;
        const __nv_bfloat16* g = B3 + (size_t)row * K3 + kk + c * 8;
        cp_async16(sw_addr(sb + B_OFF, r, c * 8), g);
    }
}

__global__ __launch_bounds__(256) void mm_bf16_split(
    const __nv_bfloat16* __restrict__ A3,
    const __nv_bfloat16* __restrict__ B3,
    float* __restrict__ C, int ldc, int N, int K3)
{
    extern __shared__ __align__(128) char smem[];
    const uint32_t sb0 = smem_u32(smem);
    const int tid = threadIdx.x;
    const int lane = tid & 31;
    const int wid = tid >> 5;
    const int wm = wid & 3;          // m group (rows wm*32)
    const int wn = wid >> 2;         // n group (cols wn*64)
    const int m0 = blockIdx.y * BM;
    const int n0 = blockIdx.x * BN;
    const int S = K3 / BK;

    float acc[2][8][4];
#pragma unroll
    for (int mt = 0; mt < 2; mt++)
#pragma unroll
        for (int nt = 0; nt < 8; nt++)
#pragma unroll
            for (int j = 0; j < 4; j++) acc[mt][nt][j] = 0.f;

    // prologue
#pragma unroll
    for (int s = 0; s < STAGES - 1; s++) {
        if (s < S) mm_load_stage(sb0 + s * STAGE_BYTES, A3, B3, K3, m0, n0, N, s * BK, tid);
        cp_commit();
    }

    // precompute ldmatrix per-lane offsets
    const int a_row = wm * 32 + (lane & 15);       // + mt*16
    const int a_kb  = (lane >> 4) * 8;             // + kk2
    const int b_nrow = wn * 64 + ((lane >> 4) << 3) + (lane & 7);   // + nt2*16
    const int b_kb  = ((lane >> 3) & 1) * 8;       // + kk2

    for (int s = 0; s < S; s++) {
        cp_wait<STAGES - 2>();
        __syncthreads();
        if (s + STAGES - 1 < S)
            mm_load_stage(sb0 + ((s + STAGES - 1) % STAGES) * STAGE_BYTES,
                          A3, B3, K3, m0, n0, N, (s + STAGES - 1) * BK, tid);
        cp_commit();

        const uint32_t sa = sb0 + (s % STAGES) * STAGE_BYTES + A_OFF;
        const uint32_t sbm = sb0 + (s % STAGES) * STAGE_BYTES + B_OFF;
#pragma unroll
        for (int k2 = 0; k2 < 2; k2++) {
            const int kk2 = k2 * 16;
            uint32_t af[2][4];
#pragma unroll
            for (int mt = 0; mt < 2; mt++)
                ldsm4(af[mt], sw_addr(sa, a_row + mt * 16, kk2 + a_kb));
            uint32_t bf[8][2];
#pragma unroll
            for (int t = 0; t < 4; t++) {
                uint32_t r[4];
                ldsm4(r, sw_addr(sbm, b_nrow + t * 16, kk2 + b_kb));
                bf[2 * t][0] = r[0]; bf[2 * t][1] = r[1];
                bf[2 * t + 1][0] = r[2]; bf[2 * t + 1][1] = r[3];
            }
#pragma unroll
            for (int mt = 0; mt < 2; mt++)
#pragma unroll
                for (int nt = 0; nt < 8; nt++)
                    mma_bf16(acc[mt][nt], af[mt], bf[nt]);
        }
        __syncthreads();
    }

    // epilogue: c0,c1 at (row, col), c2,c3 at (row+8, col)
    const int erow = m0 + wm * 32 + (lane >> 2);
    const int ecol0 = n0 + wn * 64 + (lane & 3) * 2;
#pragma unroll
    for (int mt = 0; mt < 2; mt++) {
        const int r0 = erow + mt * 16;
#pragma unroll
        for (int nt = 0; nt < 8; nt++) {
            const int col = ecol0 + nt * 8;
            if (col < N) {
                *(float2*)(C + (size_t)r0 * ldc + col) =
                    make_float2(acc[mt][nt][0], acc[mt][nt][1]);
                *(float2*)(C + (size_t)(r0 + 8) * ldc + col) =
                    make_float2(acc[mt][nt][2], acc[mt][nt][3]);
            }
        }
    }
}

// =====================================================================
// split-bf16 conversion into [R][3K].  mode 0 (A): [hi|lo|hi]
//                                      mode 1 (B): [hi|hi|lo]
// =====================================================================
__global__ void split_kernel(const float* __restrict__ src, int ld, int R, int K,
                             __nv_bfloat16* __restrict__ dst, int bmode)
{
    int idx = blockIdx.x * blockDim.x + threadIdx.x;
    if (idx >= R * K) return;
    int r = idx / K, k = idx - r * K;
    float v = src[(size_t)r * ld + k];
    __nv_bfloat16 h = __float2bfloat16(v);
    __nv_bfloat16 l = __float2bfloat16(v - __bfloat162float(h));
    __nv_bfloat16* d = dst + (size_t)r * (3 * K) + k;
    d[0] = h;
    d[K] = bmode ? h : l;
    d[2 * K] = bmode ? l : h;
}

// =====================================================================
// causal depthwise conv (K=4) + SiLU -> g_xc fp32 + A-mode split s_a_x
// =====================================================================
__global__ void conv_silu_kernel(const float* __restrict__ conv_w,
                                 const float* __restrict__ conv_b)
{
    int idx = blockIdx.x * blockDim.x + threadIdx.x;
    if (idx >= M_ROWS * D_INNER) return;
    int d = idx & (D_INNER - 1);
    int row = idx >> 12;
    int l = row & (SEQLEN - 1);

    float acc = conv_b[d];
#pragma unroll
    for (int k = 0; k < D_CONV; k++) {
        int ll = l + k - (D_CONV - 1);
        if (ll >= 0)
            acc = fmaf(g_xz[(size_t)(row + k - (D_CONV - 1)) * (2 * D_INNER) + d],
                       conv_w[d * D_CONV + k], acc);
    }
    float s = acc / (1.f + expf(-acc));
    g_xc[idx] = s;
    __nv_bfloat16 h = __float2bfloat16(s);
    __nv_bfloat16 lo = __float2bfloat16(s - __bfloat162float(h));
    __nv_bfloat16* dst = s_a_x + (size_t)row * (3 * D_INNER) + d;
    dst[0] = h; dst[D_INNER] = lo; dst[2 * D_INNER] = h;
}

__global__ void dt_softplus_kernel(const float* __restrict__ dt_b)
{
    int idx = blockIdx.x * blockDim.x + threadIdx.x;
    if (idx >= M_ROWS * D_INNER) return;
    int d = idx & (D_INNER - 1);
    float v = g_delta[idx] + dt_b[d];
    g_delta[idx] = (v > 20.f) ? v : log1pf(expf(v));
}

// =====================================================================
// selective scan: one 16-lane group per (b, d) channel
// =====================================================================
__global__ __launch_bounds__(256) void scan_kernel(const float* __restrict__ A)
{
    int t = blockIdx.x * blockDim.x + threadIdx.x;
    int lane = t & (D_STATE - 1);
    int grp = t >> 4;
    if (grp >= BATCH * D_INNER) return;
    int d = grp & (D_INNER - 1);
    int b = grp >> 12;

    const float a_l2e = A[d * D_STATE + lane] * 1.44269504088896341f;
    const float* dptr = g_delta + (size_t)b * SEQLEN * D_INNER + d;
    const float* xptr = g_xc + (size_t)b * SEQLEN * D_INNER + d;
    const float* bc = g_xdbl + (size_t)b * SEQLEN * XDBL_COLS;
    float* yp = g_y + (size_t)b * SEQLEN * D_INNER + d;

    float state = 0.f;
    for (int l = 0; l < SEQLEN; l++) {
        float dt = dptr[(size_t)l * D_INNER];
        float xv = xptr[(size_t)l * D_INNER];
        float Bn = bc[l * XDBL_COLS + DT_RANK + lane];
        float Cn = bc[l * XDBL_COLS + DT_RANK + D_STATE + lane];

        float dA = exp2f(dt * a_l2e);
        state = fmaf(dA, state, dt * Bn * xv);
        float yv = state * Cn;
        yv += __shfl_xor_sync(0xffffffffu, yv, 8);
        yv += __shfl_xor_sync(0xffffffffu, yv, 4);
        yv += __shfl_xor_sync(0xffffffffu, yv, 2);
        yv += __shfl_xor_sync(0xffffffffu, yv, 1);
        if (lane == 0) yp[(size_t)l * D_INNER] = yv;
    }
}

// =====================================================================
// gate: y = (y + xc * D[d]) * silu(z)  -> A-mode split s_a_out
// =====================================================================
__global__ void gate_split_kernel(const float* __restrict__ Dp)
{
    int idx = blockIdx.x * blockDim.x + threadIdx.x;
    if (idx >= M_ROWS * D_INNER) return;
    int d = idx & (D_INNER - 1);
    int row = idx >> 12;
    float z = g_xz[(size_t)row * (2 * D_INNER) + D_INNER + d];
    float sz = z / (1.f + expf(-z));
    float v = fmaf(g_xc[idx], Dp[d], g_y[idx]) * sz;
    __nv_bfloat16 h = __float2bfloat16(v);
    __nv_bfloat16 lo = __float2bfloat16(v - __bfloat162float(h));
    __nv_bfloat16* dst = s_a_out + (size_t)row * (3 * D_INNER) + d;
    dst[0] = h; dst[D_INNER] = lo; dst[2 * D_INNER] = h;
}

// =====================================================================
// launch
// =====================================================================
extern "C" void kernel_launch(void* const* d_in, const int* in_sizes, int n_in,
                              void* d_out, int out_size)
{
    const float* hidden     = (const float*)d_in[0];
    const float* in_proj_w  = (const float*)d_in[1];
    const float* conv_w     = (const float*)d_in[2];
    const float* conv_b     = (const float*)d_in[3];
    const float* x_proj_w   = (const float*)d_in[4];
    const float* dt_proj_w  = (const float*)d_in[5];
    const float* dt_proj_b  = (const float*)d_in[6];
    const float* out_proj_w = (const float*)d_in[7];
    const float* A_mat      = (const float*)d_in[8];
    const float* D_param    = (const float*)d_in[9];
    float* out = (float*)d_out;

    float *p_xz, *p_xdbl, *p_delta;
    __nv_bfloat16 *p_a_in, *p_w_in, *p_a_x, *p_w_x, *p_a_dt, *p_w_dt, *p_a_out, *p_w_out;
    cudaGetSymbolAddress((void**)&p_xz, g_xz);
    cudaGetSymbolAddress((void**)&p_xdbl, g_xdbl);
    cudaGetSymbolAddress((void**)&p_delta, g_delta);
    cudaGetSymbolAddress((void**)&p_a_in, s_a_in);
    cudaGetSymbolAddress((void**)&p_w_in, s_w_in);
    cudaGetSymbolAddress((void**)&p_a_x, s_a_x);
    cudaGetSymbolAddress((void**)&p_w_x, s_w_x);
    cudaGetSymbolAddress((void**)&p_a_dt, s_a_dt);
    cudaGetSymbolAddress((void**)&p_w_dt, s_w_dt);
    cudaGetSymbolAddress((void**)&p_a_out, s_a_out);
    cudaGetSymbolAddress((void**)&p_w_out, s_w_out);

    cudaFuncSetAttribute(mm_bf16_split, cudaFuncAttributeMaxDynamicSharedMemorySize, MM_SMEM);

    const int T = 256;
    const int elemBlocks = (M_ROWS * D_INNER + T - 1) / T;
    #define SPLIT(src, ld, R, K, dst, m) \
        split_kernel<<<((R) * (K) + T - 1) / T, T>>>(src, ld, R, K, dst, m)
    #define GEMM(A3, B3, C, ldc, N, K3) \
        mm_bf16_split<<<dim3(((N) + BN - 1) / BN, M_ROWS / BM), 256, MM_SMEM>>>(A3, B3, C, ldc, N, K3)

    // --- in_proj: (2048 x 8192), K3 = 6144 ---
    SPLIT(hidden, D_MODEL, M_ROWS, D_MODEL, p_a_in, 0);
    SPLIT(in_proj_w, D_MODEL, 2 * D_INNER, D_MODEL, p_w_in, 1);
    GEMM(p_a_in, p_w_in, p_xz, 2 * D_INNER, 2 * D_INNER, 3 * D_MODEL);

    // --- conv + SiLU (fused A-split) ---
    conv_silu_kernel<<<elemBlocks, T>>>(conv_w, conv_b);

    // --- x_proj: (2048 x 160), K3 = 12288 ---
    SPLIT(x_proj_w, D_INNER, XDBL_COLS, D_INNER, p_w_x, 1);
    GEMM(p_a_x, p_w_x, p_xdbl, XDBL_COLS, XDBL_COLS, 3 * D_INNER);

    // --- dt_proj: (2048 x 4096), K3 = 384 ---
    SPLIT(p_xdbl, XDBL_COLS, M_ROWS, DT_RANK, p_a_dt, 0);
    SPLIT(dt_proj_w, DT_RANK, D_INNER, DT_RANK, p_w_dt, 1);
    GEMM(p_a_dt, p_w_dt, p_delta, D_INNER, D_INNER, 3 * DT_RANK);
    dt_softplus_kernel<<<elemBlocks, T>>>(dt_proj_b);

    // --- scan ---
    scan_kernel<<<(BATCH * D_INNER * D_STATE) / 256, 256>>>(A_mat);

    // --- gate (fused A-split) ---
    gate_split_kernel<<<elemBlocks, T>>>(D_param);

    // --- out_proj: (2048 x 2048), K3 = 12288 ---
    SPLIT(out_proj_w, D_INNER, D_MODEL, D_INNER, p_w_out, 1);
    GEMM(p_a_out, p_w_out, out, D_MODEL, D_MODEL, 3 * D_INNER);

    #undef SPLIT
    #undef GEMM
}